// round 16
// baseline (speedup 1.0000x reference)
#include <cuda_runtime.h>
#include <cuda_fp16.h>
#include <math.h>
#include <stdint.h>

// Problem constants
#define B_  16
#define N_  512
#define M_  1024
#define HID_ 512
#define NH_ 8
#define HS_ 64
#define PAD_ 64
#define ROWS_T (B_*N_)   // 8192
#define ROWS_M (B_*M_)   // 16384

// ---------------- fp16 scratch ----------------------------------------------
__device__ __half g_wH   [4194304];
__device__ __half g_tgtH [(size_t)ROWS_T * HID_];
__device__ __half g_memH [(size_t)ROWS_M * HID_];
__device__ __half g_actH [(size_t)ROWS_T * HID_];
__device__ __half g_yH   [(size_t)ROWS_T * HID_];
__device__ __half g_t1H  [(size_t)ROWS_T * HID_];
__device__ __half g_t2H  [(size_t)ROWS_T * HID_];
__device__ __half g_hbH  [(size_t)ROWS_T * 4 * HID_];
__device__ __half g_qkvH [(size_t)ROWS_T * 3 * HID_];
__device__ __half g_kvH  [(size_t)ROWS_M * 2 * HID_];
__device__ __half g_qrotH[(size_t)ROWS_T * HID_];
__device__ __half g_krotH[(size_t)ROWS_M * HID_];

// ---------------- helpers -----------------------------------------------------
__device__ __forceinline__ uint32_t pack_h2(float x, float y) {
    __half2 h = __float22half2_rn(make_float2(x, y));
    return *reinterpret_cast<uint32_t*>(&h);
}
__device__ __forceinline__ void mma_f16(float* d, const uint32_t* a, const uint32_t* b) {
    asm volatile(
        "mma.sync.aligned.m16n8k16.row.col.f32.f16.f16.f32 "
        "{%0,%1,%2,%3},{%4,%5,%6,%7},{%8,%9},{%0,%1,%2,%3};"
        : "+f"(d[0]), "+f"(d[1]), "+f"(d[2]), "+f"(d[3])
        : "r"(a[0]), "r"(a[1]), "r"(a[2]), "r"(a[3]), "r"(b[0]), "r"(b[1]));
}
__device__ __forceinline__ void cp16(uint32_t saddr, const void* gptr) {
    asm volatile("cp.async.cg.shared.global [%0], [%1], 16;" :: "r"(saddr), "l"(gptr));
}
#define LDSM4(r, a) \
    asm volatile("ldmatrix.sync.aligned.m8n8.x4.shared.b16 {%0,%1,%2,%3}, [%4];" \
        : "=r"((r)[0]), "=r"((r)[1]), "=r"((r)[2]), "=r"((r)[3]) : "r"(a))
#define LDSM4T(r, a) \
    asm volatile("ldmatrix.sync.aligned.m8n8.x4.trans.shared.b16 {%0,%1,%2,%3}, [%4];" \
        : "=r"((r)[0]), "=r"((r)[1]), "=r"((r)[2]), "=r"((r)[3]) : "r"(a))

// swizzled byte offset within a [rows x 128B] tile (SW128-style)
__device__ __forceinline__ uint32_t swz128(int row, int c16) {
    int c = c16 ^ (row & 7);
    return (uint32_t)(row * 128 + c * 16);
}

// ---------------- unified conversion kernel (weights + tgt + mem) ---------------
__global__ __launch_bounds__(256) void conv_all(
    const float* __restrict__ s0, const float* __restrict__ s1,
    const float* __restrict__ s2, const float* __restrict__ s3,
    const float* __restrict__ s4, const float* __restrict__ s5,
    const float* __restrict__ s6, __half* __restrict__ W,
    const float* __restrict__ tgt, __half* __restrict__ tgtH,
    const float* __restrict__ mem, __half* __restrict__ memH)
{
    const int b = blockIdx.x;
    const float* src;
    __half* dst;
    size_t base;
    int rel;
    if (b < 4096) {
        dst = W;
        if      (b < 768)  { src = s0; base = 0;       rel = b; }
        else if (b < 1024) { src = s1; base = 786432;  rel = b - 768; }
        else if (b < 1280) { src = s2; base = 1048576; rel = b - 1024; }
        else if (b < 1792) { src = s3; base = 1310720; rel = b - 1280; }
        else if (b < 2048) { src = s4; base = 1835008; rel = b - 1792; }
        else if (b < 3072) { src = s5; base = 2097152; rel = b - 2048; }
        else               { src = s6; base = 3145728; rel = b - 3072; }
    } else if (b < 8192) {
        src = tgt; dst = tgtH; base = 0; rel = b - 4096;
    } else {
        src = mem; dst = memH; base = 0; rel = b - 8192;
    }
    const size_t i = (size_t)rel * 1024 + threadIdx.x * 4;
    float4 v = *(const float4*)(src + i);
    *(uint2*)(dst + base + i) = make_uint2(pack_h2(v.x, v.y), pack_h2(v.z, v.w));
}

// ---------------- fp16 NT GEMM (64x64 warp tile; optional fused moverz) ---------
// rotm: 0 = none, 1 = rotate all cols (head=64, out stride 512 -> KR)
//       2 = cols%128<64 rotated -> KR (stride 512); else plain -> CH
#define STG 32768
#define GEMM_SMEM (3 * STG)
__global__ __launch_bounds__(128) void gemm_h1(
    const __half* __restrict__ AH, const __half* __restrict__ BH,
    const float* __restrict__ bias, float* __restrict__ C,
    __half* __restrict__ CH, __half* __restrict__ KR,
    const float* __restrict__ sn, const float* __restrict__ cs,
    int Nc, int K, int relu, int rotm)
{
    extern __shared__ char sm[];
    const uint32_t sb = (uint32_t)__cvta_generic_to_shared(sm);
    const int t = threadIdx.x;
    const int w = t >> 5, lane = t & 31;
    const int gid = lane >> 2, tg = lane & 3;
    const int wm = w >> 1, wn = w & 1;
    const int m0 = blockIdx.y * 128, n0 = blockIdx.x * 128;
    const int KT = K >> 6;

    const int la_row = (lane & 7) + ((lane >> 3) & 1) * 8;
    const int la_c   = lane >> 4;
    const int bg        = lane >> 3;
    const int b_nt_half = bg >> 1;
    const int b_c       = bg & 1;
    const int b_row     = lane & 7;

    float acc[4][8][4];
#pragma unroll
    for (int a = 0; a < 4; a++)
#pragma unroll
        for (int bq = 0; bq < 8; bq++)
#pragma unroll
            for (int c = 0; c < 4; c++) acc[a][bq][c] = 0.f;

    auto fill = [&](int slot, int kt) {
#pragma unroll
        for (int i = 0; i < 8; i++) {
            int idx = t + i * 128;
            int row = idx >> 3, c16 = idx & 7;
            uint32_t so = (uint32_t)(slot * STG) + swz128(row, c16);
            cp16(sb + so,         AH + (size_t)(m0 + row) * K + kt * 64 + c16 * 8);
            cp16(sb + so + 16384, BH + (size_t)(n0 + row) * K + kt * 64 + c16 * 8);
        }
        asm volatile("cp.async.commit_group;");
    };

    fill(0, 0);
    if (KT > 1) fill(1, 1);

    uint32_t ahb[2][4][4], bhb[2][4][4];

    for (int kt = 0; kt < KT; kt++) {
        if (kt + 2 < KT) fill((kt + 2) % 3, kt + 2);
        if (kt + 2 < KT)      asm volatile("cp.async.wait_group 2;");
        else if (kt + 1 < KT) asm volatile("cp.async.wait_group 1;");
        else                  asm volatile("cp.async.wait_group 0;");
        __syncthreads();

        const uint32_t stg = sb + (uint32_t)((kt % 3) * STG);

#pragma unroll
        for (int ntp = 0; ntp < 4; ntp++) {
            const int rn = wn * 64 + (ntp * 2 + b_nt_half) * 8 + b_row;
            LDSM4(bhb[0][ntp], stg + 16384 + swz128(rn, b_c));
        }
#pragma unroll
        for (int mt = 0; mt < 4; mt++) {
            const int ra = wm * 64 + mt * 16 + la_row;
            LDSM4(ahb[0][mt], stg + swz128(ra, la_c));
        }

#pragma unroll
        for (int ks = 0; ks < 4; ks++) {
            const int cur = ks & 1;
            if (ks < 3) {
                const int nxt = (ks + 1) & 1;
#pragma unroll
                for (int ntp = 0; ntp < 4; ntp++) {
                    const int rn = wn * 64 + (ntp * 2 + b_nt_half) * 8 + b_row;
                    LDSM4(bhb[nxt][ntp], stg + 16384 + swz128(rn, (ks + 1) * 2 + b_c));
                }
#pragma unroll
                for (int mt = 0; mt < 4; mt++) {
                    const int ra = wm * 64 + mt * 16 + la_row;
                    LDSM4(ahb[nxt][mt], stg + swz128(ra, (ks + 1) * 2 + la_c));
                }
            }
#pragma unroll
            for (int mt = 0; mt < 4; mt++)
#pragma unroll
                for (int nt = 0; nt < 8; nt++)
                    mma_f16(acc[mt][nt], ahb[cur][mt], &bhb[cur][nt >> 1][(nt & 1) * 2]);
        }
        __syncthreads();
    }

    // epilogue
#pragma unroll
    for (int mt = 0; mt < 4; mt++) {
        const int r0 = m0 + wm * 64 + mt * 16 + gid;
        const int r1 = r0 + 8;
#pragma unroll
        for (int nt = 0; nt < 8; nt++) {
            const int col = n0 + wn * 64 + nt * 8 + tg * 2;
            const float b0 = bias ? bias[col]     : 0.f;
            const float b1 = bias ? bias[col + 1] : 0.f;
            float v0 = acc[mt][nt][0] + b0, v1 = acc[mt][nt][1] + b1;
            float v2 = acc[mt][nt][2] + b0, v3 = acc[mt][nt][3] + b1;
            if (relu) {
                v0 = fmaxf(v0, 0.f); v1 = fmaxf(v1, 0.f);
                v2 = fmaxf(v2, 0.f); v3 = fmaxf(v3, 0.f);
            }
            if (rotm == 0) {
                if (C) {
                    *(float2*)(C + (size_t)r0 * Nc + col) = make_float2(v0, v1);
                    *(float2*)(C + (size_t)r1 * Nc + col) = make_float2(v2, v3);
                }
                if (CH) {
                    *(uint32_t*)(CH + (size_t)r0 * Nc + col) = pack_h2(v0, v1);
                    *(uint32_t*)(CH + (size_t)r1 * Nc + col) = pack_h2(v2, v3);
                }
            } else if (rotm == 1) {
                const int hh = col >> 6;
                const int ii = (col & 63) >> 1;
                const float s0 = sn[(size_t)r0 * 32 + ii], c0 = cs[(size_t)r0 * 32 + ii];
                const float s1 = sn[(size_t)r1 * 32 + ii], c1 = cs[(size_t)r1 * 32 + ii];
                __half* o0 = KR + (size_t)r0 * 512 + hh * 64;
                __half* o1 = KR + (size_t)r1 * 512 + hh * 64;
                o0[ii]      = __float2half_rn(v0 * c0 - v1 * s0);
                o0[32 + ii] = __float2half_rn(v1 * c0 + v0 * s0);
                o1[ii]      = __float2half_rn(v2 * c1 - v3 * s1);
                o1[32 + ii] = __float2half_rn(v3 * c1 + v2 * s1);
            } else {
                const int hw = col & 127;
                if (hw < 64) {
                    const int hh = col >> 7;
                    const int ii = hw >> 1;
                    const float s0 = sn[(size_t)r0 * 32 + ii], c0 = cs[(size_t)r0 * 32 + ii];
                    const float s1 = sn[(size_t)r1 * 32 + ii], c1 = cs[(size_t)r1 * 32 + ii];
                    __half* o0 = KR + (size_t)r0 * 512 + hh * 64;
                    __half* o1 = KR + (size_t)r1 * 512 + hh * 64;
                    o0[ii]      = __float2half_rn(v0 * c0 - v1 * s0);
                    o0[32 + ii] = __float2half_rn(v1 * c0 + v0 * s0);
                    o1[ii]      = __float2half_rn(v2 * c1 - v3 * s1);
                    o1[32 + ii] = __float2half_rn(v3 * c1 + v2 * s1);
                } else {
                    *(uint32_t*)(CH + (size_t)r0 * Nc + col) = pack_h2(v0, v1);
                    *(uint32_t*)(CH + (size_t)r1 * Nc + col) = pack_h2(v2, v3);
                }
            }
        }
    }
}

// ---------------- fp16 flash attention: 64-key tiles, ldmatrix.trans V ----------
// smem words: Qh[64][36]@0, Kh[64][36]@2304, Vh[64][36]@4608, Ps[64][36]@6912
#define ATT_SMEM (9216 * 4)
__global__ __launch_bounds__(128) void attn_tc(
    const __half* __restrict__ Q, const __half* __restrict__ K,
    const __half* __restrict__ V, __half* __restrict__ OH,
    int NQ, int nk_rows,
    int q_rs, int q_hs, int k_rs, int k_hs, int v_rs, int v_hs,
    int ntiles_nc, int causal)
{
    extern __shared__ uint32_t usm[];
    uint32_t* Qh = usm;
    uint32_t* Kh = usm + 2304;
    uint32_t* Vh = usm + 4608;
    uint32_t* Ps = usm + 6912;
    const uint32_t vbase = (uint32_t)__cvta_generic_to_shared(Vh);

    const int qi = blockIdx.x, h = blockIdx.y, b = blockIdx.z;
    const int q0 = qi * 64;
    const int t = threadIdx.x;
    const int w = t >> 5, lane = t & 31;
    const int gid = lane >> 2, tg = lane & 3;

    const __half* Qb = Q + (size_t)b * NQ * q_rs      + (size_t)h * q_hs;
    const __half* Kb = K + (size_t)b * nk_rows * k_rs + (size_t)h * k_hs;
    const __half* Vb = V + (size_t)b * nk_rows * v_rs + (size_t)h * v_hs;

    {
        const __half2 sc = __float2half2_rn(0.125f);
#pragma unroll
        for (int i = 0; i < 4; i++) {
            int idx = t + i * 128;
            int q = idx >> 3, d8 = (idx & 7) * 8;
            uint4 x = *(const uint4*)(Qb + (size_t)(q0 + q) * q_rs + d8);
            __half2* xp = (__half2*)&x;
            const int wi = q * 36 + (d8 >> 1);
#pragma unroll
            for (int j = 0; j < 4; j++) {
                __half2 v = __hmul2(xp[j], sc);
                Qh[wi + j] = *reinterpret_cast<uint32_t*>(&v);
            }
        }
    }

    float m0r = -1e30f, m1r = -1e30f, l0s = 0.f, l1s = 0.f;
    float acc[8][4];
#pragma unroll
    for (int nt = 0; nt < 8; nt++)
#pragma unroll
        for (int c = 0; c < 4; c++) acc[nt][c] = 0.f;

    const int ntiles = causal ? (qi + 1) : ntiles_nc;
    const int qg0 = q0 + w * 16 + gid;
    const int qg1 = qg0 + 8;

    const int v_row = lane & 15;
    const int v_cw  = (lane >> 4) * 4;

    for (int kt = 0; kt < ntiles; kt++) {
        const int k0 = kt * 64;
        __syncthreads();

#pragma unroll
        for (int i = 0; i < 4; i++) {
            int idx = t + i * 128;
            int r = idx >> 3, d8 = (idx & 7) * 8;
            const int wi = r * 36 + (d8 >> 1);
            uint4 xk = *(const uint4*)(Kb + (size_t)(k0 + r) * k_rs + d8);
            const uint32_t* kw = (const uint32_t*)&xk;
            Kh[wi] = kw[0]; Kh[wi + 1] = kw[1]; Kh[wi + 2] = kw[2]; Kh[wi + 3] = kw[3];
            uint4 xv = *(const uint4*)(Vb + (size_t)(k0 + r) * v_rs + d8);
            const uint32_t* vw = (const uint32_t*)&xv;
            Vh[wi] = vw[0]; Vh[wi + 1] = vw[1]; Vh[wi + 2] = vw[2]; Vh[wi + 3] = vw[3];
        }
        __syncthreads();

        float s[8][4];
#pragma unroll
        for (int nt = 0; nt < 8; nt++)
#pragma unroll
            for (int c = 0; c < 4; c++) s[nt][c] = 0.f;

#pragma unroll
        for (int ksx = 0; ksx < 4; ksx++) {
            const int rb = w * 16;
            const int a0 = (rb + gid) * 36 + ksx * 8 + tg;
            const int a1 = (rb + gid + 8) * 36 + ksx * 8 + tg;
            uint32_t qa[4];
            qa[0] = Qh[a0]; qa[1] = Qh[a1]; qa[2] = Qh[a0 + 4]; qa[3] = Qh[a1 + 4];
#pragma unroll
            for (int nt = 0; nt < 8; nt++) {
                const int bb = (nt * 8 + gid) * 36 + ksx * 8 + tg;
                uint32_t kb[2];
                kb[0] = Kh[bb]; kb[1] = Kh[bb + 4];
                mma_f16(s[nt], qa, kb);
            }
        }

        float rmax0 = -1e30f, rmax1 = -1e30f;
#pragma unroll
        for (int nt = 0; nt < 8; nt++) {
#pragma unroll
            for (int j = 0; j < 2; j++) {
                const int cg = k0 + nt * 8 + tg * 2 + j;
                if (causal && cg > qg0) s[nt][j]     = -1e30f;
                if (causal && cg > qg1) s[nt][2 + j] = -1e30f;
                rmax0 = fmaxf(rmax0, s[nt][j]);
                rmax1 = fmaxf(rmax1, s[nt][2 + j]);
            }
        }
        rmax0 = fmaxf(rmax0, __shfl_xor_sync(0xffffffffu, rmax0, 1));
        rmax0 = fmaxf(rmax0, __shfl_xor_sync(0xffffffffu, rmax0, 2));
        rmax1 = fmaxf(rmax1, __shfl_xor_sync(0xffffffffu, rmax1, 1));
        rmax1 = fmaxf(rmax1, __shfl_xor_sync(0xffffffffu, rmax1, 2));

        const float mn0 = fmaxf(m0r, rmax0), mn1 = fmaxf(m1r, rmax1);
        const float sc0 = __expf(m0r - mn0), sc1 = __expf(m1r - mn1);
        m0r = mn0; m1r = mn1;

        float rs0 = 0.f, rs1 = 0.f;
        const int pr0 = (w * 16 + gid) * 36;
        const int pr1 = (w * 16 + gid + 8) * 36;
#pragma unroll
        for (int nt = 0; nt < 8; nt++) {
            float p00 = __expf(s[nt][0] - mn0);
            float p01 = __expf(s[nt][1] - mn0);
            float p10 = __expf(s[nt][2] - mn1);
            float p11 = __expf(s[nt][3] - mn1);
            rs0 += p00 + p01;
            rs1 += p10 + p11;
            Ps[pr0 + nt * 4 + tg] = pack_h2(p00, p01);
            Ps[pr1 + nt * 4 + tg] = pack_h2(p10, p11);
        }
        rs0 += __shfl_xor_sync(0xffffffffu, rs0, 1);
        rs0 += __shfl_xor_sync(0xffffffffu, rs0, 2);
        rs1 += __shfl_xor_sync(0xffffffffu, rs1, 1);
        rs1 += __shfl_xor_sync(0xffffffffu, rs1, 2);
        l0s = l0s * sc0 + rs0;
        l1s = l1s * sc1 + rs1;

#pragma unroll
        for (int nt = 0; nt < 8; nt++) {
            acc[nt][0] *= sc0; acc[nt][1] *= sc0;
            acc[nt][2] *= sc1; acc[nt][3] *= sc1;
        }
        __syncwarp();

#pragma unroll
        for (int ksx = 0; ksx < 4; ksx++) {
            const int a0 = (w * 16 + gid) * 36 + ksx * 8 + tg;
            const int a1 = (w * 16 + gid + 8) * 36 + ksx * 8 + tg;
            uint32_t pa[4];
            pa[0] = Ps[a0]; pa[1] = Ps[a1]; pa[2] = Ps[a0 + 4]; pa[3] = Ps[a1 + 4];
            const int vrow = ksx * 16 + v_row;
#pragma unroll
            for (int dt = 0; dt < 4; dt++) {
                uint32_t vb4[4];
                LDSM4T(vb4, vbase + (uint32_t)((vrow * 36 + dt * 8 + v_cw) << 2));
                mma_f16(acc[2 * dt],     pa, &vb4[0]);
                mma_f16(acc[2 * dt + 1], pa, &vb4[2]);
            }
        }
    }

    const float inv0 = 1.f / l0s, inv1 = 1.f / l1s;
    const int row0 = b * NQ + q0 + w * 16 + gid;
#pragma unroll
    for (int nt = 0; nt < 8; nt++) {
        const int col = h * 64 + nt * 8 + tg * 2;
        *(uint32_t*)(OH + (size_t)row0       * HID_ + col) =
            pack_h2(acc[nt][0] * inv0, acc[nt][1] * inv0);
        *(uint32_t*)(OH + (size_t)(row0 + 8) * HID_ + col) =
            pack_h2(acc[nt][2] * inv1, acc[nt][3] * inv1);
    }
}

// ---------------- fp16 residual + LayerNorm --------------------------------------
__global__ __launch_bounds__(256) void ln_h(
    const __half* __restrict__ y, const __half* __restrict__ res,
    const float* __restrict__ g, const float* __restrict__ beta,
    __half* __restrict__ outH, float* __restrict__ outF)
{
    const int row = blockIdx.x;
    const int t = threadIdx.x;
    const __half2 yv = ((const __half2*)(y   + (size_t)row * HID_))[t];
    const __half2 rv = ((const __half2*)(res + (size_t)row * HID_))[t];
    const float2 yf = __half22float2(yv);
    const float2 rf = __half22float2(rv);
    const float e0 = yf.x + rf.x;
    const float e1 = yf.y + rf.y;
    float sum = e0 + e1;
    float sq  = e0 * e0 + e1 * e1;

    __shared__ float ssum[8], ssq[8];
#pragma unroll
    for (int o = 16; o > 0; o >>= 1) {
        sum += __shfl_xor_sync(0xffffffffu, sum, o);
        sq  += __shfl_xor_sync(0xffffffffu, sq, o);
    }
    const int w = t >> 5;
    if ((t & 31) == 0) { ssum[w] = sum; ssq[w] = sq; }
    __syncthreads();
    float tot = 0.f, totsq = 0.f;
#pragma unroll
    for (int i = 0; i < 8; i++) { tot += ssum[i]; totsq += ssq[i]; }
    const float mean = tot * (1.f / HID_);
    const float var  = totsq * (1.f / HID_) - mean * mean;
    const float rstd = rsqrtf(var + 1e-5f);

    const float2 gv = ((const float2*)g)[t];
    const float2 bv = ((const float2*)beta)[t];
    const float o0 = (e0 - mean) * rstd * gv.x + bv.x;
    const float o1 = (e1 - mean) * rstd * gv.y + bv.y;
    if (outH)
        ((uint32_t*)(outH + (size_t)row * HID_))[t] = pack_h2(o0, o1);
    if (outF)
        ((float2*)(outF + (size_t)row * HID_))[t] = make_float2(o0, o1);
}

// ---------------- launch ---------------------------------------------------------
extern "C" void kernel_launch(void* const* d_in, const int* in_sizes, int n_in,
                              void* d_out, int out_size)
{
    (void)in_sizes; (void)n_in; (void)out_size;
    const float* tgt      = (const float*)d_in[0];
    const float* mem      = (const float*)d_in[1];
    const float* pep_sin  = (const float*)d_in[2];
    const float* pep_cos  = (const float*)d_in[3];
    const float* pk_sin   = (const float*)d_in[4];
    const float* pk_cos   = (const float*)d_in[5];
    const float* mmha_w   = (const float*)d_in[8];
    const float* mmha_b   = (const float*)d_in[9];
    const float* mmha_ow  = (const float*)d_in[10];
    const float* mmha_ob  = (const float*)d_in[11];
    const float* mmha_g   = (const float*)d_in[12];
    const float* mmha_be  = (const float*)d_in[13];
    const float* mha_qw   = (const float*)d_in[14];
    const float* mha_qb   = (const float*)d_in[15];
    const float* mha_kvw  = (const float*)d_in[16];
    const float* mha_kvb  = (const float*)d_in[17];
    const float* mha_ow   = (const float*)d_in[18];
    const float* mha_ob   = (const float*)d_in[19];
    const float* mha_g    = (const float*)d_in[20];
    const float* mha_be   = (const float*)d_in[21];
    const float* ffn_w1   = (const float*)d_in[22];
    const float* ffn_w2   = (const float*)d_in[23];
    const float* ffn_g    = (const float*)d_in[24];
    const float* ffn_be   = (const float*)d_in[25];
    float* out = (float*)d_out;

    __half *wH, *tgtH, *memH, *actH, *yH, *t1H, *t2H, *hbH, *qkvH, *kvH, *qrotH, *krotH;
    cudaGetSymbolAddress((void**)&wH,    g_wH);
    cudaGetSymbolAddress((void**)&tgtH,  g_tgtH);
    cudaGetSymbolAddress((void**)&memH,  g_memH);
    cudaGetSymbolAddress((void**)&actH,  g_actH);
    cudaGetSymbolAddress((void**)&yH,    g_yH);
    cudaGetSymbolAddress((void**)&t1H,   g_t1H);
    cudaGetSymbolAddress((void**)&t2H,   g_t2H);
    cudaGetSymbolAddress((void**)&hbH,   g_hbH);
    cudaGetSymbolAddress((void**)&qkvH,  g_qkvH);
    cudaGetSymbolAddress((void**)&kvH,   g_kvH);
    cudaGetSymbolAddress((void**)&qrotH, g_qrotH);
    cudaGetSymbolAddress((void**)&krotH, g_krotH);

    cudaFuncSetAttribute(gemm_h1, cudaFuncAttributeMaxDynamicSharedMemorySize, GEMM_SMEM);
    cudaFuncSetAttribute(attn_tc, cudaFuncAttributeMaxDynamicSharedMemorySize, ATT_SMEM);

    const size_t O_MMHAW = 0,        O_MMHAO = 786432, O_QW = 1048576;
    const size_t O_KVW = 1310720,    O_OW = 1835008;
    const size_t O_F1 = 2097152,     O_F2 = 3145728;

    // ---- all conversions in ONE launch ----
    conv_all<<<16384, 256>>>(mmha_w, mmha_ow, mha_qw, mha_kvw, mha_ow, ffn_w1, ffn_w2, wH,
                             tgt, tgtH, mem, memH);

    // 1) qkvH = tgt @ mmha_w^T + mmha_b (fp16)   [8192,1536]
    gemm_h1<<<dim3(1536/128, ROWS_T/128), 128, GEMM_SMEM>>>(
        tgtH, wH + O_MMHAW, mmha_b, nullptr, qkvH, nullptr, nullptr, nullptr, 1536, 512, 0, 0);

    // 2) self attention (causal) -> actH
    attn_tc<<<dim3(N_/64, NH_, B_), 128, ATT_SMEM>>>(
        qkvH, qkvH + 64, qkvH + 128, actH,
        N_, N_, 1536, 192, 1536, 192, 1536, 192, 0, 1);

    // 3) yH = attn_out @ mmha_ow^T + mmha_ob
    gemm_h1<<<dim3(512/128, ROWS_T/128), 128, GEMM_SMEM>>>(
        actH, wH + O_MMHAO, mmha_ob, nullptr, yH, nullptr, nullptr, nullptr, 512, 512, 0, 0);

    // 4) t1H = LN(yH + tgtH)
    ln_h<<<ROWS_T, 256>>>(yH, tgtH, mmha_g, mmha_be, t1H, nullptr);

    // 5) qrotH = moverz(t1H @ mha_qw^T + mha_qb)   [fused rotation]
    gemm_h1<<<dim3(512/128, ROWS_T/128), 128, GEMM_SMEM>>>(
        t1H, wH + O_QW, mha_qb, nullptr, nullptr, qrotH, pep_sin, pep_cos, 512, 512, 0, 1);

    // 6) kv GEMM with fused K rotation: krotH (K), kvH (V)   [16384,1024]
    gemm_h1<<<dim3(1024/128, ROWS_M/128), 128, GEMM_SMEM>>>(
        memH, wH + O_KVW, mha_kvb, nullptr, kvH, krotH, pk_sin, pk_cos, 1024, 512, 0, 2);

    // 7) cross attention (960 valid keys = 15 x 64) -> actH
    attn_tc<<<dim3(N_/64, NH_, B_), 128, ATT_SMEM>>>(
        qrotH, krotH, kvH + 64, actH,
        N_, M_, 512, 64, 512, 64, 1024, 128, (M_ - PAD_) / 64, 0);

    // 8) yH = attn_out @ mha_ow^T + mha_ob
    gemm_h1<<<dim3(512/128, ROWS_T/128), 128, GEMM_SMEM>>>(
        actH, wH + O_OW, mha_ob, nullptr, yH, nullptr, nullptr, nullptr, 512, 512, 0, 0);

    // 9) t2H = LN(yH + t1H)
    ln_h<<<ROWS_T, 256>>>(yH, t1H, mha_g, mha_be, t2H, nullptr);

    // 10) hbH = relu(t2H @ ffn_w1^T) (fp16)      [8192,2048]
    gemm_h1<<<dim3(2048/128, ROWS_T/128), 128, GEMM_SMEM>>>(
        t2H, wH + O_F1, nullptr, nullptr, hbH, nullptr, nullptr, nullptr, 2048, 512, 1, 0);

    // 11) yH = hbH @ ffn_w2^T (fp16, K = 2048)
    gemm_h1<<<dim3(512/128, ROWS_T/128), 128, GEMM_SMEM>>>(
        hbH, wH + O_F2, nullptr, nullptr, yH, nullptr, nullptr, nullptr, 512, 2048, 0, 0);

    // 12) out = LN(yH + t2H) -> fp32 output
    ln_h<<<ROWS_T, 256>>>(yH, t2H, ffn_g, ffn_be, nullptr, out);
}

// round 17
// speedup vs baseline: 1.0520x; 1.0520x over previous
#include <cuda_runtime.h>
#include <cuda_fp16.h>
#include <math.h>
#include <stdint.h>

// Problem constants
#define B_  16
#define N_  512
#define M_  1024
#define HID_ 512
#define NH_ 8
#define HS_ 64
#define PAD_ 64
#define ROWS_T (B_*N_)   // 8192
#define ROWS_M (B_*M_)   // 16384

// ---------------- fp16 scratch ----------------------------------------------
__device__ __half g_wH   [4194304];
__device__ __half g_tgtH [(size_t)ROWS_T * HID_];
__device__ __half g_memH [(size_t)ROWS_M * HID_];
__device__ __half g_actH [(size_t)ROWS_T * HID_];
__device__ __half g_yH   [(size_t)ROWS_T * HID_];
__device__ __half g_t1H  [(size_t)ROWS_T * HID_];
__device__ __half g_t2H  [(size_t)ROWS_T * HID_];
__device__ __half g_qH   [(size_t)ROWS_T * HID_];
__device__ __half g_hbH  [(size_t)ROWS_T * 4 * HID_];
__device__ __half g_qkvH [(size_t)ROWS_T * 3 * HID_];
__device__ __half g_kvH  [(size_t)ROWS_M * 2 * HID_];
__device__ __half g_qrotH[(size_t)ROWS_T * HID_];
__device__ __half g_krotH[(size_t)ROWS_M * HID_];

// ---------------- helpers -----------------------------------------------------
__device__ __forceinline__ uint32_t pack_h2(float x, float y) {
    __half2 h = __float22half2_rn(make_float2(x, y));
    return *reinterpret_cast<uint32_t*>(&h);
}
__device__ __forceinline__ void mma_f16(float* d, const uint32_t* a, const uint32_t* b) {
    asm volatile(
        "mma.sync.aligned.m16n8k16.row.col.f32.f16.f16.f32 "
        "{%0,%1,%2,%3},{%4,%5,%6,%7},{%8,%9},{%0,%1,%2,%3};"
        : "+f"(d[0]), "+f"(d[1]), "+f"(d[2]), "+f"(d[3])
        : "r"(a[0]), "r"(a[1]), "r"(a[2]), "r"(a[3]), "r"(b[0]), "r"(b[1]));
}
__device__ __forceinline__ void cp16(uint32_t saddr, const void* gptr) {
    asm volatile("cp.async.cg.shared.global [%0], [%1], 16;" :: "r"(saddr), "l"(gptr));
}
#define LDSM4(r, a) \
    asm volatile("ldmatrix.sync.aligned.m8n8.x4.shared.b16 {%0,%1,%2,%3}, [%4];" \
        : "=r"((r)[0]), "=r"((r)[1]), "=r"((r)[2]), "=r"((r)[3]) : "r"(a))
#define LDSM4T(r, a) \
    asm volatile("ldmatrix.sync.aligned.m8n8.x4.trans.shared.b16 {%0,%1,%2,%3}, [%4];" \
        : "=r"((r)[0]), "=r"((r)[1]), "=r"((r)[2]), "=r"((r)[3]) : "r"(a))

// swizzled byte offset within a [rows x 128B] tile (SW128-style)
__device__ __forceinline__ uint32_t swz128(int row, int c16) {
    int c = c16 ^ (row & 7);
    return (uint32_t)(row * 128 + c * 16);
}

// ---------------- unified conversion kernel (weights + tgt + mem) ---------------
__global__ __launch_bounds__(256) void conv_all(
    const float* __restrict__ s0, const float* __restrict__ s1,
    const float* __restrict__ s2, const float* __restrict__ s3,
    const float* __restrict__ s4, const float* __restrict__ s5,
    const float* __restrict__ s6, __half* __restrict__ W,
    const float* __restrict__ tgt, __half* __restrict__ tgtH,
    const float* __restrict__ mem, __half* __restrict__ memH)
{
    const int b = blockIdx.x;
    const float* src;
    __half* dst;
    size_t base;
    int rel;
    if (b < 4096) {
        dst = W;
        if      (b < 768)  { src = s0; base = 0;       rel = b; }
        else if (b < 1024) { src = s1; base = 786432;  rel = b - 768; }
        else if (b < 1280) { src = s2; base = 1048576; rel = b - 1024; }
        else if (b < 1792) { src = s3; base = 1310720; rel = b - 1280; }
        else if (b < 2048) { src = s4; base = 1835008; rel = b - 1792; }
        else if (b < 3072) { src = s5; base = 2097152; rel = b - 2048; }
        else               { src = s6; base = 3145728; rel = b - 3072; }
    } else if (b < 8192) {
        src = tgt; dst = tgtH; base = 0; rel = b - 4096;
    } else {
        src = mem; dst = memH; base = 0; rel = b - 8192;
    }
    const size_t i = (size_t)rel * 1024 + threadIdx.x * 4;
    float4 v = *(const float4*)(src + i);
    *(uint2*)(dst + base + i) = make_uint2(pack_h2(v.x, v.y), pack_h2(v.z, v.w));
}

// ---------------- fp16 NT GEMM (64x64 warp tile, pipelined fragments) -----------
#define STG 32768
#define GEMM_SMEM (3 * STG)
__global__ __launch_bounds__(128) void gemm_h1(
    const __half* __restrict__ AH, const __half* __restrict__ BH,
    const float* __restrict__ bias, float* __restrict__ C,
    __half* __restrict__ CH,
    int Nc, int K, int relu)
{
    extern __shared__ char sm[];
    const uint32_t sb = (uint32_t)__cvta_generic_to_shared(sm);
    const int t = threadIdx.x;
    const int w = t >> 5, lane = t & 31;
    const int gid = lane >> 2, tg = lane & 3;
    const int wm = w >> 1, wn = w & 1;
    const int m0 = blockIdx.y * 128, n0 = blockIdx.x * 128;
    const int KT = K >> 6;

    const int la_row = (lane & 7) + ((lane >> 3) & 1) * 8;
    const int la_c   = lane >> 4;
    const int bg        = lane >> 3;
    const int b_nt_half = bg >> 1;
    const int b_c       = bg & 1;
    const int b_row     = lane & 7;

    float acc[4][8][4];
#pragma unroll
    for (int a = 0; a < 4; a++)
#pragma unroll
        for (int bq = 0; bq < 8; bq++)
#pragma unroll
            for (int c = 0; c < 4; c++) acc[a][bq][c] = 0.f;

    auto fill = [&](int slot, int kt) {
#pragma unroll
        for (int i = 0; i < 8; i++) {
            int idx = t + i * 128;
            int row = idx >> 3, c16 = idx & 7;
            uint32_t so = (uint32_t)(slot * STG) + swz128(row, c16);
            cp16(sb + so,         AH + (size_t)(m0 + row) * K + kt * 64 + c16 * 8);
            cp16(sb + so + 16384, BH + (size_t)(n0 + row) * K + kt * 64 + c16 * 8);
        }
        asm volatile("cp.async.commit_group;");
    };

    fill(0, 0);
    if (KT > 1) fill(1, 1);

    uint32_t ahb[2][4][4], bhb[2][4][4];

    for (int kt = 0; kt < KT; kt++) {
        if (kt + 2 < KT) fill((kt + 2) % 3, kt + 2);
        if (kt + 2 < KT)      asm volatile("cp.async.wait_group 2;");
        else if (kt + 1 < KT) asm volatile("cp.async.wait_group 1;");
        else                  asm volatile("cp.async.wait_group 0;");
        __syncthreads();

        const uint32_t stg = sb + (uint32_t)((kt % 3) * STG);

#pragma unroll
        for (int ntp = 0; ntp < 4; ntp++) {
            const int rn = wn * 64 + (ntp * 2 + b_nt_half) * 8 + b_row;
            LDSM4(bhb[0][ntp], stg + 16384 + swz128(rn, b_c));
        }
#pragma unroll
        for (int mt = 0; mt < 4; mt++) {
            const int ra = wm * 64 + mt * 16 + la_row;
            LDSM4(ahb[0][mt], stg + swz128(ra, la_c));
        }

#pragma unroll
        for (int ks = 0; ks < 4; ks++) {
            const int cur = ks & 1;
            if (ks < 3) {
                const int nxt = (ks + 1) & 1;
#pragma unroll
                for (int ntp = 0; ntp < 4; ntp++) {
                    const int rn = wn * 64 + (ntp * 2 + b_nt_half) * 8 + b_row;
                    LDSM4(bhb[nxt][ntp], stg + 16384 + swz128(rn, (ks + 1) * 2 + b_c));
                }
#pragma unroll
                for (int mt = 0; mt < 4; mt++) {
                    const int ra = wm * 64 + mt * 16 + la_row;
                    LDSM4(ahb[nxt][mt], stg + swz128(ra, (ks + 1) * 2 + la_c));
                }
            }
#pragma unroll
            for (int mt = 0; mt < 4; mt++)
#pragma unroll
                for (int nt = 0; nt < 8; nt++)
                    mma_f16(acc[mt][nt], ahb[cur][mt], &bhb[cur][nt >> 1][(nt & 1) * 2]);
        }
        __syncthreads();
    }

#pragma unroll
    for (int mt = 0; mt < 4; mt++) {
        const int r0 = m0 + wm * 64 + mt * 16 + gid;
#pragma unroll
        for (int nt = 0; nt < 8; nt++) {
            const int col = n0 + wn * 64 + nt * 8 + tg * 2;
            const float b0 = bias ? bias[col]     : 0.f;
            const float b1 = bias ? bias[col + 1] : 0.f;
            float v0 = acc[mt][nt][0] + b0, v1 = acc[mt][nt][1] + b1;
            float v2 = acc[mt][nt][2] + b0, v3 = acc[mt][nt][3] + b1;
            if (relu) {
                v0 = fmaxf(v0, 0.f); v1 = fmaxf(v1, 0.f);
                v2 = fmaxf(v2, 0.f); v3 = fmaxf(v3, 0.f);
            }
            if (C) {
                *(float2*)(C + (size_t)r0       * Nc + col) = make_float2(v0, v1);
                *(float2*)(C + (size_t)(r0 + 8) * Nc + col) = make_float2(v2, v3);
            }
            if (CH) {
                *(uint32_t*)(CH + (size_t)r0       * Nc + col) = pack_h2(v0, v1);
                *(uint32_t*)(CH + (size_t)(r0 + 8) * Nc + col) = pack_h2(v2, v3);
            }
        }
    }
}

// ---------------- fp16 flash attention: 64-key tiles, ldmatrix.trans V ----------
// smem words: Qh[64][36]@0, Kh[64][36]@2304, Vh[64][36]@4608, Ps[64][36]@6912
#define ATT_SMEM (9216 * 4)
__global__ __launch_bounds__(128) void attn_tc(
    const __half* __restrict__ Q, const __half* __restrict__ K,
    const __half* __restrict__ V, __half* __restrict__ OH,
    int NQ, int nk_rows,
    int q_rs, int q_hs, int k_rs, int k_hs, int v_rs, int v_hs,
    int ntiles_nc, int causal)
{
    extern __shared__ uint32_t usm[];
    uint32_t* Qh = usm;
    uint32_t* Kh = usm + 2304;
    uint32_t* Vh = usm + 4608;
    uint32_t* Ps = usm + 6912;
    const uint32_t vbase = (uint32_t)__cvta_generic_to_shared(Vh);

    const int qi = blockIdx.x, h = blockIdx.y, b = blockIdx.z;
    const int q0 = qi * 64;
    const int t = threadIdx.x;
    const int w = t >> 5, lane = t & 31;
    const int gid = lane >> 2, tg = lane & 3;

    const __half* Qb = Q + (size_t)b * NQ * q_rs      + (size_t)h * q_hs;
    const __half* Kb = K + (size_t)b * nk_rows * k_rs + (size_t)h * k_hs;
    const __half* Vb = V + (size_t)b * nk_rows * v_rs + (size_t)h * v_hs;

    {
        const __half2 sc = __float2half2_rn(0.125f);
#pragma unroll
        for (int i = 0; i < 4; i++) {
            int idx = t + i * 128;
            int q = idx >> 3, d8 = (idx & 7) * 8;
            uint4 x = *(const uint4*)(Qb + (size_t)(q0 + q) * q_rs + d8);
            __half2* xp = (__half2*)&x;
            const int wi = q * 36 + (d8 >> 1);
#pragma unroll
            for (int j = 0; j < 4; j++) {
                __half2 v = __hmul2(xp[j], sc);
                Qh[wi + j] = *reinterpret_cast<uint32_t*>(&v);
            }
        }
    }

    float m0r = -1e30f, m1r = -1e30f, l0s = 0.f, l1s = 0.f;
    float acc[8][4];
#pragma unroll
    for (int nt = 0; nt < 8; nt++)
#pragma unroll
        for (int c = 0; c < 4; c++) acc[nt][c] = 0.f;

    const int ntiles = causal ? (qi + 1) : ntiles_nc;
    const int qg0 = q0 + w * 16 + gid;
    const int qg1 = qg0 + 8;

    const int v_row = lane & 15;
    const int v_cw  = (lane >> 4) * 4;

    for (int kt = 0; kt < ntiles; kt++) {
        const int k0 = kt * 64;
        __syncthreads();

#pragma unroll
        for (int i = 0; i < 4; i++) {
            int idx = t + i * 128;
            int r = idx >> 3, d8 = (idx & 7) * 8;
            const int wi = r * 36 + (d8 >> 1);
            uint4 xk = *(const uint4*)(Kb + (size_t)(k0 + r) * k_rs + d8);
            const uint32_t* kw = (const uint32_t*)&xk;
            Kh[wi] = kw[0]; Kh[wi + 1] = kw[1]; Kh[wi + 2] = kw[2]; Kh[wi + 3] = kw[3];
            uint4 xv = *(const uint4*)(Vb + (size_t)(k0 + r) * v_rs + d8);
            const uint32_t* vw = (const uint32_t*)&xv;
            Vh[wi] = vw[0]; Vh[wi + 1] = vw[1]; Vh[wi + 2] = vw[2]; Vh[wi + 3] = vw[3];
        }
        __syncthreads();

        float s[8][4];
#pragma unroll
        for (int nt = 0; nt < 8; nt++)
#pragma unroll
            for (int c = 0; c < 4; c++) s[nt][c] = 0.f;

#pragma unroll
        for (int ksx = 0; ksx < 4; ksx++) {
            const int rb = w * 16;
            const int a0 = (rb + gid) * 36 + ksx * 8 + tg;
            const int a1 = (rb + gid + 8) * 36 + ksx * 8 + tg;
            uint32_t qa[4];
            qa[0] = Qh[a0]; qa[1] = Qh[a1]; qa[2] = Qh[a0 + 4]; qa[3] = Qh[a1 + 4];
#pragma unroll
            for (int nt = 0; nt < 8; nt++) {
                const int bb = (nt * 8 + gid) * 36 + ksx * 8 + tg;
                uint32_t kb[2];
                kb[0] = Kh[bb]; kb[1] = Kh[bb + 4];
                mma_f16(s[nt], qa, kb);
            }
        }

        float rmax0 = -1e30f, rmax1 = -1e30f;
#pragma unroll
        for (int nt = 0; nt < 8; nt++) {
#pragma unroll
            for (int j = 0; j < 2; j++) {
                const int cg = k0 + nt * 8 + tg * 2 + j;
                if (causal && cg > qg0) s[nt][j]     = -1e30f;
                if (causal && cg > qg1) s[nt][2 + j] = -1e30f;
                rmax0 = fmaxf(rmax0, s[nt][j]);
                rmax1 = fmaxf(rmax1, s[nt][2 + j]);
            }
        }
        rmax0 = fmaxf(rmax0, __shfl_xor_sync(0xffffffffu, rmax0, 1));
        rmax0 = fmaxf(rmax0, __shfl_xor_sync(0xffffffffu, rmax0, 2));
        rmax1 = fmaxf(rmax1, __shfl_xor_sync(0xffffffffu, rmax1, 1));
        rmax1 = fmaxf(rmax1, __shfl_xor_sync(0xffffffffu, rmax1, 2));

        const float mn0 = fmaxf(m0r, rmax0), mn1 = fmaxf(m1r, rmax1);
        const float sc0 = __expf(m0r - mn0), sc1 = __expf(m1r - mn1);
        m0r = mn0; m1r = mn1;

        float rs0 = 0.f, rs1 = 0.f;
        const int pr0 = (w * 16 + gid) * 36;
        const int pr1 = (w * 16 + gid + 8) * 36;
#pragma unroll
        for (int nt = 0; nt < 8; nt++) {
            float p00 = __expf(s[nt][0] - mn0);
            float p01 = __expf(s[nt][1] - mn0);
            float p10 = __expf(s[nt][2] - mn1);
            float p11 = __expf(s[nt][3] - mn1);
            rs0 += p00 + p01;
            rs1 += p10 + p11;
            Ps[pr0 + nt * 4 + tg] = pack_h2(p00, p01);
            Ps[pr1 + nt * 4 + tg] = pack_h2(p10, p11);
        }
        rs0 += __shfl_xor_sync(0xffffffffu, rs0, 1);
        rs0 += __shfl_xor_sync(0xffffffffu, rs0, 2);
        rs1 += __shfl_xor_sync(0xffffffffu, rs1, 1);
        rs1 += __shfl_xor_sync(0xffffffffu, rs1, 2);
        l0s = l0s * sc0 + rs0;
        l1s = l1s * sc1 + rs1;

#pragma unroll
        for (int nt = 0; nt < 8; nt++) {
            acc[nt][0] *= sc0; acc[nt][1] *= sc0;
            acc[nt][2] *= sc1; acc[nt][3] *= sc1;
        }
        __syncwarp();

#pragma unroll
        for (int ksx = 0; ksx < 4; ksx++) {
            const int a0 = (w * 16 + gid) * 36 + ksx * 8 + tg;
            const int a1 = (w * 16 + gid + 8) * 36 + ksx * 8 + tg;
            uint32_t pa[4];
            pa[0] = Ps[a0]; pa[1] = Ps[a1]; pa[2] = Ps[a0 + 4]; pa[3] = Ps[a1 + 4];
            const int vrow = ksx * 16 + v_row;
#pragma unroll
            for (int dt = 0; dt < 4; dt++) {
                uint32_t vb4[4];
                LDSM4T(vb4, vbase + (uint32_t)((vrow * 36 + dt * 8 + v_cw) << 2));
                mma_f16(acc[2 * dt],     pa, &vb4[0]);
                mma_f16(acc[2 * dt + 1], pa, &vb4[2]);
            }
        }
    }

    const float inv0 = 1.f / l0s, inv1 = 1.f / l1s;
    const int row0 = b * NQ + q0 + w * 16 + gid;
#pragma unroll
    for (int nt = 0; nt < 8; nt++) {
        const int col = h * 64 + nt * 8 + tg * 2;
        *(uint32_t*)(OH + (size_t)row0       * HID_ + col) =
            pack_h2(acc[nt][0] * inv0, acc[nt][1] * inv0);
        *(uint32_t*)(OH + (size_t)(row0 + 8) * HID_ + col) =
            pack_h2(acc[nt][2] * inv1, acc[nt][3] * inv1);
    }
}

// ---------------- moverz rotation (fp16 -> fp16) --------------------------------
__global__ __launch_bounds__(256) void rot_h(
    const __half* __restrict__ X, const float* __restrict__ sn,
    const float* __restrict__ cs, __half* __restrict__ Out,
    int x_rs, int x_hs)
{
    const int idx = blockIdx.x * 256 + threadIdx.x;
    const int i  = idx & 31;
    const int h  = (idx >> 5) & 7;
    const int rn = idx >> 8;
    const __half* xb = X + (size_t)rn * x_rs + h * x_hs;
    const float x0 = __half2float(xb[2 * i]);
    const float x1 = __half2float(xb[2 * i + 1]);
    const float s = sn[(size_t)rn * 32 + i];
    const float c = cs[(size_t)rn * 32 + i];
    __half* ob = Out + ((size_t)rn * NH_ + h) * 64;
    ob[i]      = __float2half_rn(x0 * c - x1 * s);
    ob[32 + i] = __float2half_rn(x1 * c + x0 * s);
}

// ---------------- fp16 residual + LayerNorm --------------------------------------
__global__ __launch_bounds__(256) void ln_h(
    const __half* __restrict__ y, const __half* __restrict__ res,
    const float* __restrict__ g, const float* __restrict__ beta,
    __half* __restrict__ outH, float* __restrict__ outF)
{
    const int row = blockIdx.x;
    const int t = threadIdx.x;
    const __half2 yv = ((const __half2*)(y   + (size_t)row * HID_))[t];
    const __half2 rv = ((const __half2*)(res + (size_t)row * HID_))[t];
    const float2 yf = __half22float2(yv);
    const float2 rf = __half22float2(rv);
    const float e0 = yf.x + rf.x;
    const float e1 = yf.y + rf.y;
    float sum = e0 + e1;
    float sq  = e0 * e0 + e1 * e1;

    __shared__ float ssum[8], ssq[8];
#pragma unroll
    for (int o = 16; o > 0; o >>= 1) {
        sum += __shfl_xor_sync(0xffffffffu, sum, o);
        sq  += __shfl_xor_sync(0xffffffffu, sq, o);
    }
    const int w = t >> 5;
    if ((t & 31) == 0) { ssum[w] = sum; ssq[w] = sq; }
    __syncthreads();
    float tot = 0.f, totsq = 0.f;
#pragma unroll
    for (int i = 0; i < 8; i++) { tot += ssum[i]; totsq += ssq[i]; }
    const float mean = tot * (1.f / HID_);
    const float var  = totsq * (1.f / HID_) - mean * mean;
    const float rstd = rsqrtf(var + 1e-5f);

    const float2 gv = ((const float2*)g)[t];
    const float2 bv = ((const float2*)beta)[t];
    const float o0 = (e0 - mean) * rstd * gv.x + bv.x;
    const float o1 = (e1 - mean) * rstd * gv.y + bv.y;
    if (outH)
        ((uint32_t*)(outH + (size_t)row * HID_))[t] = pack_h2(o0, o1);
    if (outF)
        ((float2*)(outF + (size_t)row * HID_))[t] = make_float2(o0, o1);
}

// ---------------- launch ---------------------------------------------------------
extern "C" void kernel_launch(void* const* d_in, const int* in_sizes, int n_in,
                              void* d_out, int out_size)
{
    (void)in_sizes; (void)n_in; (void)out_size;
    const float* tgt      = (const float*)d_in[0];
    const float* mem      = (const float*)d_in[1];
    const float* pep_sin  = (const float*)d_in[2];
    const float* pep_cos  = (const float*)d_in[3];
    const float* pk_sin   = (const float*)d_in[4];
    const float* pk_cos   = (const float*)d_in[5];
    const float* mmha_w   = (const float*)d_in[8];
    const float* mmha_b   = (const float*)d_in[9];
    const float* mmha_ow  = (const float*)d_in[10];
    const float* mmha_ob  = (const float*)d_in[11];
    const float* mmha_g   = (const float*)d_in[12];
    const float* mmha_be  = (const float*)d_in[13];
    const float* mha_qw   = (const float*)d_in[14];
    const float* mha_qb   = (const float*)d_in[15];
    const float* mha_kvw  = (const float*)d_in[16];
    const float* mha_kvb  = (const float*)d_in[17];
    const float* mha_ow   = (const float*)d_in[18];
    const float* mha_ob   = (const float*)d_in[19];
    const float* mha_g    = (const float*)d_in[20];
    const float* mha_be   = (const float*)d_in[21];
    const float* ffn_w1   = (const float*)d_in[22];
    const float* ffn_w2   = (const float*)d_in[23];
    const float* ffn_g    = (const float*)d_in[24];
    const float* ffn_be   = (const float*)d_in[25];
    float* out = (float*)d_out;

    __half *wH, *tgtH, *memH, *actH, *yH, *t1H, *t2H, *qH, *hbH, *qkvH, *kvH, *qrotH, *krotH;
    cudaGetSymbolAddress((void**)&wH,    g_wH);
    cudaGetSymbolAddress((void**)&tgtH,  g_tgtH);
    cudaGetSymbolAddress((void**)&memH,  g_memH);
    cudaGetSymbolAddress((void**)&actH,  g_actH);
    cudaGetSymbolAddress((void**)&yH,    g_yH);
    cudaGetSymbolAddress((void**)&t1H,   g_t1H);
    cudaGetSymbolAddress((void**)&t2H,   g_t2H);
    cudaGetSymbolAddress((void**)&qH,    g_qH);
    cudaGetSymbolAddress((void**)&hbH,   g_hbH);
    cudaGetSymbolAddress((void**)&qkvH,  g_qkvH);
    cudaGetSymbolAddress((void**)&kvH,   g_kvH);
    cudaGetSymbolAddress((void**)&qrotH, g_qrotH);
    cudaGetSymbolAddress((void**)&krotH, g_krotH);

    cudaFuncSetAttribute(gemm_h1, cudaFuncAttributeMaxDynamicSharedMemorySize, GEMM_SMEM);
    cudaFuncSetAttribute(attn_tc, cudaFuncAttributeMaxDynamicSharedMemorySize, ATT_SMEM);

    const size_t O_MMHAW = 0,        O_MMHAO = 786432, O_QW = 1048576;
    const size_t O_KVW = 1310720,    O_OW = 1835008;
    const size_t O_F1 = 2097152,     O_F2 = 3145728;

    // ---- all conversions in ONE launch ----
    conv_all<<<16384, 256>>>(mmha_w, mmha_ow, mha_qw, mha_kvw, mha_ow, ffn_w1, ffn_w2, wH,
                             tgt, tgtH, mem, memH);

    // 1) qkvH = tgt @ mmha_w^T + mmha_b (fp16)   [8192,1536]
    gemm_h1<<<dim3(1536/128, ROWS_T/128), 128, GEMM_SMEM>>>(
        tgtH, wH + O_MMHAW, mmha_b, nullptr, qkvH, 1536, 512, 0);

    // 2) self attention (causal) -> actH
    attn_tc<<<dim3(N_/64, NH_, B_), 128, ATT_SMEM>>>(
        qkvH, qkvH + 64, qkvH + 128, actH,
        N_, N_, 1536, 192, 1536, 192, 1536, 192, 0, 1);

    // 3) yH = attn_out @ mmha_ow^T + mmha_ob
    gemm_h1<<<dim3(512/128, ROWS_T/128), 128, GEMM_SMEM>>>(
        actH, wH + O_MMHAO, mmha_ob, nullptr, yH, 512, 512, 0);

    // 4) t1H = LN(yH + tgtH)
    ln_h<<<ROWS_T, 256>>>(yH, tgtH, mmha_g, mmha_be, t1H, nullptr);

    // 5) qH = t1H @ mha_qw^T + mha_qb (fp16)
    gemm_h1<<<dim3(512/128, ROWS_T/128), 128, GEMM_SMEM>>>(
        t1H, wH + O_QW, mha_qb, nullptr, qH, 512, 512, 0);

    // 6) qrotH = moverz(qH)
    rot_h<<<ROWS_T, 256>>>(qH, pep_sin, pep_cos, qrotH, 512, 64);

    // 7) kvH = mem @ mha_kvw^T + mha_kvb (fp16)  [16384,1024]
    gemm_h1<<<dim3(1024/128, ROWS_M/128), 128, GEMM_SMEM>>>(
        memH, wH + O_KVW, mha_kvb, nullptr, kvH, 1024, 512, 0);

    // 8) krotH = moverz(kvH[..., :64])
    rot_h<<<ROWS_M, 256>>>(kvH, pk_sin, pk_cos, krotH, 1024, 128);

    // 9) cross attention (960 valid keys = 15 x 64) -> actH
    attn_tc<<<dim3(N_/64, NH_, B_), 128, ATT_SMEM>>>(
        qrotH, krotH, kvH + 64, actH,
        N_, M_, 512, 64, 512, 64, 1024, 128, (M_ - PAD_) / 64, 0);

    // 10) yH = attn_out @ mha_ow^T + mha_ob
    gemm_h1<<<dim3(512/128, ROWS_T/128), 128, GEMM_SMEM>>>(
        actH, wH + O_OW, mha_ob, nullptr, yH, 512, 512, 0);

    // 11) t2H = LN(yH + t1H)
    ln_h<<<ROWS_T, 256>>>(yH, t1H, mha_g, mha_be, t2H, nullptr);

    // 12) hbH = relu(t2H @ ffn_w1^T) (fp16)      [8192,2048]
    gemm_h1<<<dim3(2048/128, ROWS_T/128), 128, GEMM_SMEM>>>(
        t2H, wH + O_F1, nullptr, nullptr, hbH, 2048, 512, 1);

    // 13) yH = hbH @ ffn_w2^T (fp16, K = 2048)
    gemm_h1<<<dim3(512/128, ROWS_T/128), 128, GEMM_SMEM>>>(
        hbH, wH + O_F2, nullptr, nullptr, yH, 512, 2048, 0);

    // 14) out = LN(yH + t2H) -> fp32 output
    ln_h<<<ROWS_T, 256>>>(yH, t2H, ffn_g, ffn_be, nullptr, out);
}